// round 9
// baseline (speedup 1.0000x reference)
#include <cuda_runtime.h>
#include <cuda_bf16.h>
#include <cstdint>

// WindowAttention via mma.sync.m16n8k16 bf16, 3-term split (fp32-accurate to
// ~1e-5). One window per CTA, 256 threads (8 warps), 8192 CTAs.
//
// All bf16 operand tiles row-major [outdim][k], hi/lo pair tiles.
// Row strides chosen ≡ 16 (mod 128) bytes => conflict-free ldmatrix.

#define ASTR 272   // 136 bf16: A-region / Q / K / W row stride (bytes)
#define VSTR 144   // 72 bf16: VT row stride (bytes)

#define AH_ 0u          // A: X -> P(head pair) -> O, [64][136]
#define AL_ 17408u
#define QH_ 34816u      // Q [64][136] (token, channel) pre-scaled
#define QL_ 52224u
#define KH_ 69632u      // K [64][136] (key, channel)
#define KL_ 87040u
#define VH_ 104448u     // VT [128][72] (channel, token)
#define VL_ 122880u
#define WH_ 141312u     // W^T stage [128][136]; overlaid by Sarr fp32 [4][64][68]
#define WL_ 176128u
#define SARR_ 141312u
#define MSK_ 210944u    // mask fp32 [2401]
#define RI_  220560u    // rel_index uint16 [2401]
#define TAB_ 225376u    // bias table fp32 [676]
#define QB_  228080u    // qkv_b fp32 [384]
#define PB_  229616u    // proj_b fp32 [128]
#define SMEMB 230128u

extern __shared__ char smem[];

__device__ __forceinline__ uint32_t s2u(const void* p){
    uint32_t a;
    asm("{ .reg .u64 t; cvta.to.shared.u64 t, %1; cvt.u32.u64 %0, t; }":"=r"(a):"l"(p));
    return a;
}
__device__ __forceinline__ void ldm4(uint32_t addr, uint32_t* f){
    asm volatile("ldmatrix.sync.aligned.m8n8.x4.shared.b16 {%0,%1,%2,%3}, [%4];"
        :"=r"(f[0]),"=r"(f[1]),"=r"(f[2]),"=r"(f[3]):"r"(addr));
}
__device__ __forceinline__ void mma_bf16(float* c, const uint32_t* a, uint32_t b0, uint32_t b1){
    asm volatile("mma.sync.aligned.m16n8k16.row.col.f32.bf16.bf16.f32 "
        "{%0,%1,%2,%3},{%4,%5,%6,%7},{%8,%9},{%0,%1,%2,%3};"
        :"+f"(c[0]),"+f"(c[1]),"+f"(c[2]),"+f"(c[3])
        :"r"(a[0]),"r"(a[1]),"r"(a[2]),"r"(a[3]),"r"(b0),"r"(b1));
}
// split pair (a,b) into packed hi bf16x2 (ret) and lo bf16x2 (out param)
__device__ __forceinline__ uint32_t packhl(float a, float b, uint32_t& lo){
    __nv_bfloat16 ha=__float2bfloat16_rn(a), hb=__float2bfloat16_rn(b);
    __nv_bfloat16 la=__float2bfloat16_rn(a-__bfloat162float(ha));
    __nv_bfloat16 lb=__float2bfloat16_rn(b-__bfloat162float(hb));
    lo=(uint32_t)__bfloat16_as_ushort(la)|((uint32_t)__bfloat16_as_ushort(lb)<<16);
    return (uint32_t)__bfloat16_as_ushort(ha)|((uint32_t)__bfloat16_as_ushort(hb)<<16);
}
__device__ __forceinline__ void split1(float v,__nv_bfloat16&h,__nv_bfloat16&l){
    h=__float2bfloat16_rn(v); l=__float2bfloat16_rn(v-__bfloat162float(h));
}

// C[MT*16 x 32] += A[.. x 16*KS] * B^T, 3-term split. A stride = ASTR, B stride = bStr.
template<int MT,int KS>
__device__ __forceinline__ void gemm_tile(float* cacc,
    uint32_t aH, uint32_t aL, uint32_t bH, uint32_t bL, int bStr, int lane)
{
    const int rowA=(lane&7)+((lane>>3)&1)*8;
    const int colA=(lane>>4)*8;
    const int rowB=(lane&7)+((lane>>4)&1)*8;
    const int colB=((lane>>3)&1)*8;
    #pragma unroll
    for(int s=0;s<KS;s++){
        const int k0=s*16;
        uint32_t ah[MT][4], al[MT][4], bh[2][4], bl[2][4];
        #pragma unroll
        for(int mt=0;mt<MT;mt++){
            uint32_t o=(uint32_t)((mt*16+rowA)*ASTR+(k0+colA)*2);
            ldm4(aH+o,ah[mt]); ldm4(aL+o,al[mt]);
        }
        #pragma unroll
        for(int nt=0;nt<2;nt++){
            uint32_t o=(uint32_t)((nt*16+rowB)*bStr+(k0+colB)*2);
            ldm4(bH+o,bh[nt]); ldm4(bL+o,bl[nt]);
        }
        #pragma unroll
        for(int mt=0;mt<MT;mt++)
            #pragma unroll
            for(int n=0;n<4;n++){
                float* c=cacc+(mt*4+n)*4;
                uint32_t h0=bh[n>>1][(n&1)*2], h1=bh[n>>1][(n&1)*2+1];
                uint32_t l0=bl[n>>1][(n&1)*2], l1=bl[n>>1][(n&1)*2+1];
                mma_bf16(c,ah[mt],h0,h1);   // Ah*Bh
                mma_bf16(c,ah[mt],l0,l1);   // Ah*Bl
                mma_bf16(c,al[mt],h0,h1);   // Al*Bh
            }
    }
}

__global__ __launch_bounds__(256,1)
void winattn_hmma_kernel(const float* __restrict__ x, const float* __restrict__ mask,
                         const float* __restrict__ qkv_w, const float* __restrict__ qkv_b,
                         const float* __restrict__ btable, const float* __restrict__ proj_w,
                         const float* __restrict__ proj_b, const int* __restrict__ rel_index,
                         float* __restrict__ out)
{
    const int tid=threadIdx.x, wid=tid>>5, lane=tid&31;
    const int b=blockIdx.x;
    const uint32_t sb=s2u(smem);
    float* qb=(float*)(smem+QB_); float* pb=(float*)(smem+PB_);
    float* maskS=(float*)(smem+MSK_); uint16_t* riS=(uint16_t*)(smem+RI_);
    float* tabS=(float*)(smem+TAB_);
    const float scale=0.17677669529663687f;

    // ---- zero A pad rows 49..63 (only X phase needs it; later phases rewrite)
    for(int t=tid;t<1020;t+=256){
        int r=49+t/68, c=(t%68)*4;
        *(uint32_t*)(smem+AH_+(uint32_t)(r*ASTR+c))=0;
        *(uint32_t*)(smem+AL_+(uint32_t)(r*ASTR+c))=0;
    }
    // ---- tables
    if(tid<128){ pb[tid]=proj_b[tid]; qb[tid]=qkv_b[tid];
                 qb[128+tid]=qkv_b[128+tid]; qb[256+tid]=qkv_b[256+tid]; }
    for(int t=tid;t<2401;t+=256){
        maskS[t]=mask[(size_t)b*2401+t];
        riS[t]=(uint16_t)rel_index[t];
    }
    for(int t=tid;t<676;t+=256) tabS[t]=btable[t];
    // ---- X -> A hi/lo
    {
        const float* xg=x+(size_t)b*49*128;
        for(int t=tid;t<49*32;t+=256){
            int r=t>>5, c4=(t&31)<<2;
            float4 v=*(const float4*)&xg[r*128+c4];
            uint32_t lo0,lo1, hi0=packhl(v.x,v.y,lo0), hi1=packhl(v.z,v.w,lo1);
            uint32_t o=(uint32_t)(r*ASTR+c4*2);
            *(uint32_t*)(smem+AH_+o)=hi0; *(uint32_t*)(smem+AH_+o+4)=hi1;
            *(uint32_t*)(smem+AL_+o)=lo0; *(uint32_t*)(smem+AL_+o+4)=lo1;
        }
    }
    __syncthreads();

    const int m0=(wid&1)*32, n0=(wid>>1)*32;   // 64x128 C tiling, 8 warps

    // ================= qkv GEMM: 3 chunks (q,k,v) of 128 cols ===============
    for(int c=0;c<3;c++){
        if(c) __syncthreads();                  // W reuse
        for(int t=tid;t<4096;t+=256){           // stage W^T[n][k] hi/lo
            int k=t>>5, n4=(t&31)<<2;
            float4 v=*(const float4*)&qkv_w[(size_t)k*384+c*128+n4];
            float vv[4]={v.x,v.y,v.z,v.w};
            #pragma unroll
            for(int j=0;j<4;j++){
                __nv_bfloat16 h,l; split1(vv[j],h,l);
                uint32_t o=(uint32_t)((n4+j)*ASTR+k*2);
                *(__nv_bfloat16*)(smem+WH_+o)=h; *(__nv_bfloat16*)(smem+WL_+o)=l;
            }
        }
        __syncthreads();

        float cacc[32];
        #pragma unroll
        for(int t=0;t<32;t++) cacc[t]=0.f;
        gemm_tile<2,8>(cacc, sb+AH_+m0*ASTR, sb+AL_+m0*ASTR,
                             sb+WH_+n0*ASTR, sb+WL_+n0*ASTR, ASTR, lane);
        // extraction
        #pragma unroll
        for(int mt=0;mt<2;mt++){
            int r0=m0+mt*16+(lane>>2);
            #pragma unroll
            for(int n=0;n<4;n++){
                int col=n0+n*8+(lane&3)*2;
                const float* cc=cacc+(mt*4+n)*4;
                if(c==0){
                    uint32_t lo,hi;
                    hi=packhl((cc[0]+qb[col])*scale,(cc[1]+qb[col+1])*scale,lo);
                    *(uint32_t*)(smem+QH_+(uint32_t)(r0*ASTR+col*2))=hi;
                    *(uint32_t*)(smem+QL_+(uint32_t)(r0*ASTR+col*2))=lo;
                    hi=packhl((cc[2]+qb[col])*scale,(cc[3]+qb[col+1])*scale,lo);
                    *(uint32_t*)(smem+QH_+(uint32_t)((r0+8)*ASTR+col*2))=hi;
                    *(uint32_t*)(smem+QL_+(uint32_t)((r0+8)*ASTR+col*2))=lo;
                } else if(c==1){
                    uint32_t lo,hi;
                    hi=packhl(cc[0]+qb[128+col],cc[1]+qb[128+col+1],lo);
                    *(uint32_t*)(smem+KH_+(uint32_t)(r0*ASTR+col*2))=hi;
                    *(uint32_t*)(smem+KL_+(uint32_t)(r0*ASTR+col*2))=lo;
                    hi=packhl(cc[2]+qb[128+col],cc[3]+qb[128+col+1],lo);
                    *(uint32_t*)(smem+KH_+(uint32_t)((r0+8)*ASTR+col*2))=hi;
                    *(uint32_t*)(smem+KL_+(uint32_t)((r0+8)*ASTR+col*2))=lo;
                } else {                        // V: transposed store VT[ch][tok]
                    #pragma unroll
                    for(int e=0;e<4;e++){
                        int ch=col+(e&1), row=r0+(e>>1)*8;
                        __nv_bfloat16 h,l; split1(cc[e]+qb[256+ch],h,l);
                        uint32_t o=(uint32_t)(ch*VSTR+row*2);
                        *(__nv_bfloat16*)(smem+VH_+o)=h;
                        *(__nv_bfloat16*)(smem+VL_+o)=l;
                    }
                }
            }
        }
    }
    __syncthreads();

    // ================= S = Q K^T, all 4 heads -> Sarr fp32 ==================
    {
        const int wl=wid&3, g=wid>>2;
        const int m0s=(wl&1)*32, n0s=(wl>>1)*32;
        #pragma unroll
        for(int p=0;p<2;p++){
            const int h=2*p+g;
            float cacc[32];
            #pragma unroll
            for(int t=0;t<32;t++) cacc[t]=0.f;
            gemm_tile<2,2>(cacc, sb+QH_+m0s*ASTR+h*64, sb+QL_+m0s*ASTR+h*64,
                                 sb+KH_+n0s*ASTR+h*64, sb+KL_+n0s*ASTR+h*64, ASTR, lane);
            #pragma unroll
            for(int mt=0;mt<2;mt++){
                int r0=m0s+mt*16+(lane>>2);
                #pragma unroll
                for(int n=0;n<4;n++){
                    int col=n0s+n*8+(lane&3)*2;
                    const float* cc=cacc+(mt*4+n)*4;
                    *(float2*)(smem+SARR_+(uint32_t)(h*17408+r0*272+col*4))
                        =make_float2(cc[0],cc[1]);
                    *(float2*)(smem+SARR_+(uint32_t)(h*17408+(r0+8)*272+col*4))
                        =make_float2(cc[2],cc[3]);
                }
            }
        }
    }
    __syncthreads();

    // ================= softmax (+bias +mask), 196 threads ===================
    if(tid<196){
        int h=tid/49, q=tid-h*49;
        float* row=(float*)(smem+SARR_+(uint32_t)(h*17408+q*272));
        const float* mrow=maskS+q*49;
        const uint16_t* rr=riS+q*49;
        float mx=-1e30f;
        for(int j=0;j<49;j++){
            float t=row[j]+tabS[rr[j]*4+h]+mrow[j];
            row[j]=t; mx=fmaxf(mx,t);
        }
        float s=0.f;
        for(int j=0;j<49;j++){ float e=__expf(row[j]-mx); row[j]=e; s+=e; }
        float inv=1.f/s;
        for(int j=0;j<49;j++) row[j]*=inv;
    }
    __syncthreads();

    // ================= P conversion + AV (2 head-pair passes) ===============
    const int wl=wid&3, g=wid>>2, m0v=wl*16;
    float oacc[2][16];
    #pragma unroll
    for(int p=0;p<2;p++){
        // P(heads 2p,2p+1) -> A tiles; zeros at pad rows/cols
        for(int e=tid;e<4096;e+=256){
            int hp=e>>11, rem=e&2047, row=rem>>5, col=(rem&31)*2;
            int h=2*p+hp;
            float v0=0.f,v1=0.f;
            if(row<49){
                const float* sr=(const float*)(smem+SARR_+(uint32_t)(h*17408+row*272));
                if(col<49) v0=sr[col];
                if(col+1<49) v1=sr[col+1];
            }
            uint32_t lo, hi=packhl(v0,v1,lo);
            uint32_t o=(uint32_t)(row*ASTR+(hp*64+col)*2);
            *(uint32_t*)(smem+AH_+o)=hi; *(uint32_t*)(smem+AL_+o)=lo;
        }
        __syncthreads();
        const int h=2*p+g;
        #pragma unroll
        for(int t=0;t<16;t++) oacc[p][t]=0.f;
        gemm_tile<1,4>(oacc[p], sb+AH_+m0v*ASTR+g*128, sb+AL_+m0v*ASTR+g*128,
                                sb+VH_+h*32*VSTR, sb+VL_+h*32*VSTR, VSTR, lane);
        __syncthreads();
    }

    // ---- O frags -> A tiles (bf16 hi/lo) ----
    #pragma unroll
    for(int p=0;p<2;p++){
        const int h=2*p+g;
        int r0=m0v+(lane>>2);
        #pragma unroll
        for(int n=0;n<4;n++){
            int col=h*32+n*8+(lane&3)*2;
            const float* cc=&oacc[p][n*4];
            uint32_t lo,hi;
            hi=packhl(cc[0],cc[1],lo);
            *(uint32_t*)(smem+AH_+(uint32_t)(r0*ASTR+col*2))=hi;
            *(uint32_t*)(smem+AL_+(uint32_t)(r0*ASTR+col*2))=lo;
            hi=packhl(cc[2],cc[3],lo);
            *(uint32_t*)(smem+AH_+(uint32_t)((r0+8)*ASTR+col*2))=hi;
            *(uint32_t*)(smem+AL_+(uint32_t)((r0+8)*ASTR+col*2))=lo;
        }
    }
    // ---- stage proj_w^T (Sarr dead) ----
    for(int t=tid;t<4096;t+=256){
        int k=t>>5, n4=(t&31)<<2;
        float4 v=*(const float4*)&proj_w[(size_t)k*128+n4];
        float vv[4]={v.x,v.y,v.z,v.w};
        #pragma unroll
        for(int j=0;j<4;j++){
            __nv_bfloat16 h,l; split1(vv[j],h,l);
            uint32_t o=(uint32_t)((n4+j)*ASTR+k*2);
            *(__nv_bfloat16*)(smem+WH_+o)=h; *(__nv_bfloat16*)(smem+WL_+o)=l;
        }
    }
    __syncthreads();

    // ================= proj GEMM + output ===================================
    {
        float cacc[32];
        #pragma unroll
        for(int t=0;t<32;t++) cacc[t]=0.f;
        gemm_tile<2,8>(cacc, sb+AH_+m0*ASTR, sb+AL_+m0*ASTR,
                             sb+WH_+n0*ASTR, sb+WL_+n0*ASTR, ASTR, lane);
        float* og=out+(size_t)b*49*128;
        #pragma unroll
        for(int mt=0;mt<2;mt++){
            int r0=m0+mt*16+(lane>>2);
            #pragma unroll
            for(int n=0;n<4;n++){
                int col=n0+n*8+(lane&3)*2;
                const float* cc=cacc+(mt*4+n)*4;
                if(r0<49)
                    *(float2*)&og[r0*128+col]
                        =make_float2(cc[0]+pb[col],cc[1]+pb[col+1]);
                if(r0+8<49)
                    *(float2*)&og[(r0+8)*128+col]
                        =make_float2(cc[2]+pb[col],cc[3]+pb[col+1]);
            }
        }
    }
}

extern "C" void kernel_launch(void* const* d_in, const int* in_sizes, int n_in,
                              void* d_out, int out_size)
{
    const float* x      =(const float*)d_in[0];
    const float* mask   =(const float*)d_in[1];
    const float* qkv_w  =(const float*)d_in[2];
    const float* qkv_b  =(const float*)d_in[3];
    const float* btable =(const float*)d_in[4];
    const float* proj_w =(const float*)d_in[5];
    const float* proj_b =(const float*)d_in[6];
    const int*   rel_idx=(const int*)d_in[7];
    float* out=(float*)d_out;

    const int Bwin=in_sizes[0]/(49*128);   // 8192
    cudaFuncSetAttribute(winattn_hmma_kernel,
                         cudaFuncAttributeMaxDynamicSharedMemorySize, SMEMB);
    winattn_hmma_kernel<<<Bwin,256,SMEMB>>>(
        x,mask,qkv_w,qkv_b,btable,proj_w,proj_b,rel_idx,out);
}

// round 11
// speedup vs baseline: 1.6748x; 1.6748x over previous
#include <cuda_runtime.h>
#include <cuda_bf16.h>
#include <cstdint>

// WindowAttention via mma.sync.m16n8k16 bf16, 3-term split (~1e-5 accurate).
// One window per CTA, 256 threads (8 warps), 8192 CTAs.
//
// All operands stored in their NATURAL layout (conflict-free stores);
// K-major consumers use ldmatrix.x4.trans. No smem transposes anywhere.

#define ASTR 272   // 136 bf16 row stride (bytes) for all bf16 tiles

#define AH_ 0u          // A: X -> P(head pair) -> O, [64 tok][136]
#define AL_ 17408u
#define QH_ 34816u      // Q [64 tok][136 ch] pre-scaled
#define QL_ 52224u
#define KH_ 69632u      // K [64 tok][136 ch]
#define KL_ 87040u
#define VH_ 104448u     // V [64 tok][136 ch]  (trans-loaded as AV B operand)
#define VL_ 121856u
#define WH_ 139264u     // W stage [128 k][136 n]; overlaid by Sarr fp32 [4][64][68]
#define WL_ 174080u
#define SARR_ 139264u
#define MSK_ 208896u    // mask fp32 [2401]
#define RI_  218504u    // rel_index uint16 [2401]
#define TAB_ 223312u    // bias table fp32 [676]
#define QB_  226016u    // qkv_b fp32 [384]
#define PB_  227552u    // proj_b fp32 [128]
#define SMEMB 228064u

extern __shared__ char smem[];

__device__ __forceinline__ uint32_t s2u(const void* p){
    uint32_t a;
    asm("{ .reg .u64 t; cvta.to.shared.u64 t, %1; cvt.u32.u64 %0, t; }":"=r"(a):"l"(p));
    return a;
}
__device__ __forceinline__ void ldm4(uint32_t addr, uint32_t* f){
    asm volatile("ldmatrix.sync.aligned.m8n8.x4.shared.b16 {%0,%1,%2,%3}, [%4];"
        :"=r"(f[0]),"=r"(f[1]),"=r"(f[2]),"=r"(f[3]):"r"(addr));
}
__device__ __forceinline__ void ldm4t(uint32_t addr, uint32_t* f){
    asm volatile("ldmatrix.sync.aligned.m8n8.x4.trans.shared.b16 {%0,%1,%2,%3}, [%4];"
        :"=r"(f[0]),"=r"(f[1]),"=r"(f[2]),"=r"(f[3]):"r"(addr));
}
__device__ __forceinline__ void mma_bf16(float* c, const uint32_t* a, uint32_t b0, uint32_t b1){
    asm volatile("mma.sync.aligned.m16n8k16.row.col.f32.bf16.bf16.f32 "
        "{%0,%1,%2,%3},{%4,%5,%6,%7},{%8,%9},{%0,%1,%2,%3};"
        :"+f"(c[0]),"+f"(c[1]),"+f"(c[2]),"+f"(c[3])
        :"r"(a[0]),"r"(a[1]),"r"(a[2]),"r"(a[3]),"r"(b0),"r"(b1));
}
__device__ __forceinline__ uint32_t packhl(float a, float b, uint32_t& lo){
    __nv_bfloat16 ha=__float2bfloat16_rn(a), hb=__float2bfloat16_rn(b);
    __nv_bfloat16 la=__float2bfloat16_rn(a-__bfloat162float(ha));
    __nv_bfloat16 lb=__float2bfloat16_rn(b-__bfloat162float(hb));
    lo=(uint32_t)__bfloat16_as_ushort(la)|((uint32_t)__bfloat16_as_ushort(lb)<<16);
    return (uint32_t)__bfloat16_as_ushort(ha)|((uint32_t)__bfloat16_as_ushort(hb)<<16);
}

// C[MT*16 x 32] += A * B^T(logical), 3-term split.
// BT=false: B stored [n][k] (non-trans load). BT=true: B stored [k][n] (trans load).
template<int MT,int KS,bool BT>
__device__ __forceinline__ void gemm_tile(float* cacc,
    uint32_t aH, uint32_t aL, uint32_t bH, uint32_t bL, int lane)
{
    const int rowA=lane&15, colA=(lane>>4)*8;
    #pragma unroll
    for(int s=0;s<KS;s++){
        const int k0=s*16;
        uint32_t ah[MT][4], al[MT][4], bh[2][4], bl[2][4];
        #pragma unroll
        for(int mt=0;mt<MT;mt++){
            uint32_t o=(uint32_t)((mt*16+rowA)*ASTR+(k0+colA)*2);
            ldm4(aH+o,ah[mt]); ldm4(aL+o,al[mt]);
        }
        #pragma unroll
        for(int nt=0;nt<2;nt++){
            if(BT){   // [k][n]: rows=k, cols=n; trans load; same quadrant order
                uint32_t o=(uint32_t)((k0+(lane&15))*ASTR+(nt*16+(lane>>4)*8)*2);
                ldm4t(bH+o,bh[nt]); ldm4t(bL+o,bl[nt]);
            } else {  // [n][k]
                uint32_t o=(uint32_t)((nt*16+((lane&7)+((lane>>4)&1)*8))*ASTR
                                      +(k0+(((lane>>3)&1)*8))*2);
                ldm4(bH+o,bh[nt]); ldm4(bL+o,bl[nt]);
            }
        }
        #pragma unroll
        for(int mt=0;mt<MT;mt++)
            #pragma unroll
            for(int n=0;n<4;n++){
                float* c=cacc+(mt*4+n)*4;
                uint32_t h0=bh[n>>1][(n&1)*2], h1=bh[n>>1][(n&1)*2+1];
                uint32_t l0=bl[n>>1][(n&1)*2], l1=bl[n>>1][(n&1)*2+1];
                mma_bf16(c,ah[mt],h0,h1);
                mma_bf16(c,ah[mt],l0,l1);
                mma_bf16(c,al[mt],h0,h1);
            }
    }
}

// stage W[k][cb..cb+127] as [k][n] hi/lo, conflict-free STS.64
__device__ __forceinline__ void stageW(const float* __restrict__ w,int ldw,int cb,int tid){
    for(int t=tid;t<4096;t+=256){
        int k=t>>5, n4=(t&31)<<2;
        float4 v=*(const float4*)&w[(size_t)k*ldw+cb+n4];
        uint32_t lo0,lo1, hi0=packhl(v.x,v.y,lo0), hi1=packhl(v.z,v.w,lo1);
        uint32_t o=(uint32_t)(k*ASTR+n4*2);
        *(uint2*)(smem+WH_+o)=make_uint2(hi0,hi1);
        *(uint2*)(smem+WL_+o)=make_uint2(lo0,lo1);
    }
}

__global__ __launch_bounds__(256,1)
void winattn_hmma_kernel(const float* __restrict__ x, const float* __restrict__ mask,
                         const float* __restrict__ qkv_w, const float* __restrict__ qkv_b,
                         const float* __restrict__ btable, const float* __restrict__ proj_w,
                         const float* __restrict__ proj_b, const int* __restrict__ rel_index,
                         float* __restrict__ out)
{
    const int tid=threadIdx.x, wid=tid>>5, lane=tid&31;
    const int b=blockIdx.x;
    const uint32_t sb=s2u(smem);
    float* qb=(float*)(smem+QB_); float* pb=(float*)(smem+PB_);
    float* maskS=(float*)(smem+MSK_); uint16_t* riS=(uint16_t*)(smem+RI_);
    float* tabS=(float*)(smem+TAB_);
    const float scale=0.17677669529663687f;

    // ---- zero A pad rows 49..63 (X phase; later phases rewrite all rows) ----
    for(int t=tid;t<1020;t+=256){
        int r=49+t/68, c=(t%68)*4;
        *(uint32_t*)(smem+AH_+(uint32_t)(r*ASTR+c))=0;
        *(uint32_t*)(smem+AL_+(uint32_t)(r*ASTR+c))=0;
    }
    // ---- tables ----
    if(tid<128){ pb[tid]=proj_b[tid]; qb[tid]=qkv_b[tid];
                 qb[128+tid]=qkv_b[128+tid]; qb[256+tid]=qkv_b[256+tid]; }
    for(int t=tid;t<2401;t+=256){
        maskS[t]=mask[(size_t)b*2401+t];
        riS[t]=(uint16_t)rel_index[t];
    }
    for(int t=tid;t<676;t+=256) tabS[t]=btable[t];
    // ---- X -> A hi/lo (natural layout, conflict-free) ----
    {
        const float* xg=x+(size_t)b*49*128;
        for(int t=tid;t<49*32;t+=256){
            int r=t>>5, c4=(t&31)<<2;
            float4 v=*(const float4*)&xg[r*128+c4];
            uint32_t lo0,lo1, hi0=packhl(v.x,v.y,lo0), hi1=packhl(v.z,v.w,lo1);
            uint32_t o=(uint32_t)(r*ASTR+c4*2);
            *(uint2*)(smem+AH_+o)=make_uint2(hi0,hi1);
            *(uint2*)(smem+AL_+o)=make_uint2(lo0,lo1);
        }
    }
    __syncthreads();

    const int m0=(wid&1)*32, n0=(wid>>1)*32;   // 64x128 C tiling, 8 warps

    // ================= qkv GEMM: 3 chunks (q,k,v) of 128 cols ===============
    for(int c=0;c<3;c++){
        if(c) __syncthreads();                  // W region reuse
        stageW(qkv_w,384,c*128,tid);
        __syncthreads();

        float cacc[32];
        #pragma unroll
        for(int t=0;t<32;t++) cacc[t]=0.f;
        gemm_tile<2,8,true>(cacc, sb+AH_+m0*ASTR, sb+AL_+m0*ASTR,
                                  sb+WH_+n0*2,    sb+WL_+n0*2, lane);
        // extraction: all three dests natural [tok][ch] layout, conflict-free
        const uint32_t dH = (c==0)?QH_:((c==1)?KH_:VH_);
        const uint32_t dL = (c==0)?QL_:((c==1)?KL_:VL_);
        const int bof=c*128;
        const float sc=(c==0)?scale:1.f;
        #pragma unroll
        for(int mt=0;mt<2;mt++){
            int r0=m0+mt*16+(lane>>2);
            #pragma unroll
            for(int n=0;n<4;n++){
                int col=n0+n*8+(lane&3)*2;
                const float* cc=cacc+(mt*4+n)*4;
                uint32_t lo,hi;
                hi=packhl((cc[0]+qb[bof+col])*sc,(cc[1]+qb[bof+col+1])*sc,lo);
                *(uint32_t*)(smem+dH+(uint32_t)(r0*ASTR+col*2))=hi;
                *(uint32_t*)(smem+dL+(uint32_t)(r0*ASTR+col*2))=lo;
                hi=packhl((cc[2]+qb[bof+col])*sc,(cc[3]+qb[bof+col+1])*sc,lo);
                *(uint32_t*)(smem+dH+(uint32_t)((r0+8)*ASTR+col*2))=hi;
                *(uint32_t*)(smem+dL+(uint32_t)((r0+8)*ASTR+col*2))=lo;
            }
        }
    }
    __syncthreads();

    // ================= S = Q K^T, all 4 heads -> Sarr fp32 ==================
    {
        const int wl=wid&3, g=wid>>2;
        const int m0s=(wl&1)*32, n0s=(wl>>1)*32;
        #pragma unroll
        for(int p=0;p<2;p++){
            const int h=2*p+g;
            float cacc[32];
            #pragma unroll
            for(int t=0;t<32;t++) cacc[t]=0.f;
            gemm_tile<2,2,false>(cacc, sb+QH_+m0s*ASTR+h*64, sb+QL_+m0s*ASTR+h*64,
                                       sb+KH_+n0s*ASTR+h*64, sb+KL_+n0s*ASTR+h*64, lane);
            #pragma unroll
            for(int mt=0;mt<2;mt++){
                int r0=m0s+mt*16+(lane>>2);
                #pragma unroll
                for(int n=0;n<4;n++){
                    int col=n0s+n*8+(lane&3)*2;
                    const float* cc=cacc+(mt*4+n)*4;
                    *(float2*)(smem+SARR_+(uint32_t)(h*17408+r0*272+col*4))
                        =make_float2(cc[0],cc[1]);
                    *(float2*)(smem+SARR_+(uint32_t)(h*17408+(r0+8)*272+col*4))
                        =make_float2(cc[2],cc[3]);
                }
            }
        }
    }
    __syncthreads();

    // ================= softmax (+bias +mask), 196 threads ===================
    if(tid<196){
        int h=tid/49, q=tid-h*49;
        float* row=(float*)(smem+SARR_+(uint32_t)(h*17408+q*272));
        const float* mrow=maskS+q*49;
        const uint16_t* rr=riS+q*49;
        float mx=-1e30f;
        for(int j=0;j<49;j++){
            float t=row[j]+tabS[rr[j]*4+h]+mrow[j];
            row[j]=t; mx=fmaxf(mx,t);
        }
        float s=0.f;
        for(int j=0;j<49;j++){ float e=__expf(row[j]-mx); row[j]=e; s+=e; }
        float inv=1.f/s;
        for(int j=0;j<49;j++) row[j]*=inv;
    }
    __syncthreads();

    // ================= P conversion + AV (2 head-pair passes) ===============
    const int wl=wid&3, g=wid>>2, m0v=wl*16;
    float oacc[2][16];
    #pragma unroll
    for(int p=0;p<2;p++){
        // P(heads 2p,2p+1) -> A tiles [q][tok]; zeros at pad rows/cols
        for(int e=tid;e<4096;e+=256){
            int hp=e>>11, rem=e&2047, row=rem>>5, col=(rem&31)*2;
            int h=2*p+hp;
            float v0=0.f,v1=0.f;
            if(row<49){
                const float* sr=(const float*)(smem+SARR_+(uint32_t)(h*17408+row*272));
                if(col<49) v0=sr[col];
                if(col+1<49) v1=sr[col+1];
            }
            uint32_t lo, hi=packhl(v0,v1,lo);
            uint32_t o=(uint32_t)(row*ASTR+(hp*64+col)*2);
            *(uint32_t*)(smem+AH_+o)=hi; *(uint32_t*)(smem+AL_+o)=lo;
        }
        __syncthreads();
        const int h=2*p+g;
        #pragma unroll
        for(int t=0;t<16;t++) oacc[p][t]=0.f;
        // A = P rows m0v.., cols g*64.. ; B = V[tok][ch] trans, ch base h*32
        gemm_tile<1,4,true>(oacc[p], sb+AH_+m0v*ASTR+g*128, sb+AL_+m0v*ASTR+g*128,
                                     sb+VH_+h*64,           sb+VL_+h*64, lane);
        __syncthreads();
    }

    // ---- O frags -> A tiles [tok][ch] (bf16 hi/lo, conflict-free) ----
    #pragma unroll
    for(int p=0;p<2;p++){
        const int h=2*p+g;
        int r0=m0v+(lane>>2);
        #pragma unroll
        for(int n=0;n<4;n++){
            int col=h*32+n*8+(lane&3)*2;
            const float* cc=&oacc[p][n*4];
            uint32_t lo,hi;
            hi=packhl(cc[0],cc[1],lo);
            *(uint32_t*)(smem+AH_+(uint32_t)(r0*ASTR+col*2))=hi;
            *(uint32_t*)(smem+AL_+(uint32_t)(r0*ASTR+col*2))=lo;
            hi=packhl(cc[2],cc[3],lo);
            *(uint32_t*)(smem+AH_+(uint32_t)((r0+8)*ASTR+col*2))=hi;
            *(uint32_t*)(smem+AL_+(uint32_t)((r0+8)*ASTR+col*2))=lo;
        }
    }
    __syncthreads();          // Sarr reads done; stage proj_w over it
    stageW(proj_w,128,0,tid);
    __syncthreads();

    // ================= proj GEMM + output ===================================
    {
        float cacc[32];
        #pragma unroll
        for(int t=0;t<32;t++) cacc[t]=0.f;
        gemm_tile<2,8,true>(cacc, sb+AH_+m0*ASTR, sb+AL_+m0*ASTR,
                                  sb+WH_+n0*2,    sb+WL_+n0*2, lane);
        float* og=out+(size_t)b*49*128;
        #pragma unroll
        for(int mt=0;mt<2;mt++){
            int r0=m0+mt*16+(lane>>2);
            #pragma unroll
            for(int n=0;n<4;n++){
                int col=n0+n*8+(lane&3)*2;
                const float* cc=cacc+(mt*4+n)*4;
                if(r0<49)
                    *(float2*)&og[r0*128+col]
                        =make_float2(cc[0]+pb[col],cc[1]+pb[col+1]);
                if(r0+8<49)
                    *(float2*)&og[(r0+8)*128+col]
                        =make_float2(cc[2]+pb[col],cc[3]+pb[col+1]);
            }
        }
    }
}

extern "C" void kernel_launch(void* const* d_in, const int* in_sizes, int n_in,
                              void* d_out, int out_size)
{
    const float* x      =(const float*)d_in[0];
    const float* mask   =(const float*)d_in[1];
    const float* qkv_w  =(const float*)d_in[2];
    const float* qkv_b  =(const float*)d_in[3];
    const float* btable =(const float*)d_in[4];
    const float* proj_w =(const float*)d_in[5];
    const float* proj_b =(const float*)d_in[6];
    const int*   rel_idx=(const int*)d_in[7];
    float* out=(float*)d_out;

    const int Bwin=in_sizes[0]/(49*128);   // 8192
    cudaFuncSetAttribute(winattn_hmma_kernel,
                         cudaFuncAttributeMaxDynamicSharedMemorySize, SMEMB);
    winattn_hmma_kernel<<<Bwin,256,SMEMB>>>(
        x,mask,qkv_w,qkv_b,btable,proj_w,proj_b,rel_idx,out);
}